// round 13
// baseline (speedup 1.0000x reference)
#include <cuda_runtime.h>
#include <cuda_bf16.h>
#include <cstdint>
#include <math.h>

// Problem constants (fixed by setup_inputs: S=2048, U=10, D=256)
#define B_TOT 20480
#define D_DIM 256
#define S_CLS 2048
#define U_UTT 10
#define EPSF  1e-8f
#define LOG2E 1.4426950408889634f
#define N_ROWTILES (B_TOT / 128)   // 160
#define N_COLTILES (S_CLS / 128)   // 16

// Scratch (static __device__ arrays: allocation-free per harness rules)
__device__ __nv_bfloat16 g_Enh[(size_t)B_TOT * D_DIM];  // normalized embeddings bf16
__device__ __nv_bfloat16 g_Cnh[(size_t)S_CLS * D_DIM];  // normalized centroids bf16 (x log2e)
__device__ float g_rowsum[B_TOT];                       // sum_k exp(sim[row,k])
__device__ float g_pos[B_TOT];                          // sim[row, label(row)]
__device__ unsigned g_cnt[N_ROWTILES];                  // col-tile completion counters

// ===========================================================================
// helpers
// ===========================================================================
__device__ __forceinline__ uint32_t smem_to_u32(const void* p) {
    uint32_t a;
    asm("{ .reg .u64 t; cvta.to.shared.u64 t, %1; cvt.u32.u64 %0, t; }"
        : "=r"(a) : "l"(p));
    return a;
}
__device__ __forceinline__ void cp16(uint32_t dst, const void* src) {
    asm volatile("cp.async.cg.shared.global [%0], [%1], 16;"
                 :: "r"(dst), "l"(src) : "memory");
}
__device__ __forceinline__ float warpSum(float v) {
    #pragma unroll
    for (int o = 16; o; o >>= 1) v += __shfl_xor_sync(0xffffffffu, v, o);
    return v;
}
__device__ __forceinline__ float dot4(float4 a, float4 b) {
    return a.x*b.x + a.y*b.y + a.z*b.z + a.w*b.w;
}
__device__ __forceinline__ uint32_t pack_bf16x2(float lo, float hi) {
    __nv_bfloat162 p = __float22bfloat162_rn(make_float2(lo, hi));
    return *reinterpret_cast<uint32_t*>(&p);
}
__device__ __forceinline__ float ex2f(float x) {
    float r;
    asm("ex2.approx.ftz.f32 %0, %1;" : "=f"(r) : "f"(x));
    return r;
}
// release+acquire fetch-add on a global counter (flag pattern; NO membar/L1 flush)
__device__ __forceinline__ unsigned atom_add_acq_rel(unsigned* p, unsigned v) {
    unsigned old;
    asm volatile("atom.add.acq_rel.gpu.global.u32 %0, [%1], %2;"
                 : "=r"(old) : "l"(p), "r"(v) : "memory");
    return old;
}

// ---------------------------------------------------------------------------
// Kernel 1 (fused pre-pass): block per speaker, 320 threads = 10 warps.
// Centroid (cross-warp smem sum) -> L2 norm -> g_Cnh scaled by log2e.
// Rows L2-normalized -> g_Enh. pos[row] fp32 vs unscaled smem centroid.
// Zeroes this speaker's 10 rowsum slots, the row-tile counters, and out[0].
// ---------------------------------------------------------------------------
__global__ __launch_bounds__(320)
void pre_kernel(const float* __restrict__ emb, float* __restrict__ out) {
    __shared__ __align__(16) float rowS[U_UTT][D_DIM];
    __shared__ __align__(16) float cnS[D_DIM];
    __shared__ float red[16];
    const int s    = blockIdx.x;
    const int u    = threadIdx.x >> 5;
    const int lane = threadIdx.x & 31;
    const int t    = threadIdx.x;
    if (s == 0 && t == 0) out[0] = 0.0f;
    if (t < U_UTT) g_rowsum[s * U_UTT + t] = 0.0f;
    if (s < N_ROWTILES && t == 319) g_cnt[s] = 0u;

    const float4* pr = (const float4*)(emb + ((size_t)s * U_UTT + u) * D_DIM);
    float4 a = pr[lane], b = pr[lane + 32];
    ((float4*)rowS[u])[lane]      = a;
    ((float4*)rowS[u])[lane + 32] = b;
    __syncthreads();

    float c = 0.0f;
    if (t < D_DIM) {
        #pragma unroll
        for (int uu = 0; uu < U_UTT; uu++) c += rowS[uu][t];
        c *= (1.0f / U_UTT);
    }
    float sq = warpSum(c * c);
    if (lane == 0) red[u] = sq;
    __syncthreads();
    if (t < 32) {
        float v = (lane < U_UTT) ? red[lane] : 0.0f;
        v = warpSum(v);
        if (lane == 0) red[0] = v;
    }
    __syncthreads();
    const float cnorm = fmaxf(sqrtf(red[0]), EPSF);
    if (t < D_DIM) {
        float cn = c / cnorm;
        cnS[t] = cn;
        g_Cnh[(size_t)s * D_DIM + t] = __float2bfloat16(cn * LOG2E);
    }
    __syncthreads();

    float sqr = warpSum(dot4(a, a) + dot4(b, b));
    float sc = 1.0f / fmaxf(sqrtf(sqr), EPSF);
    a.x *= sc; a.y *= sc; a.z *= sc; a.w *= sc;
    b.x *= sc; b.y *= sc; b.z *= sc; b.w *= sc;
    const size_t row = (size_t)s * U_UTT + u;
    uint2* outh = (uint2*)(g_Enh + row * D_DIM);
    outh[lane]      = make_uint2(pack_bf16x2(a.x, a.y), pack_bf16x2(a.z, a.w));
    outh[lane + 32] = make_uint2(pack_bf16x2(b.x, b.y), pack_bf16x2(b.z, b.w));
    const float4* pc = (const float4*)cnS;
    float v = dot4(a, pc[lane]) + dot4(b, pc[lane + 32]);
    v = warpSum(v);
    if (lane == 0) g_pos[row] = v;
}

// ---------------------------------------------------------------------------
// Kernel 2: bf16 mma.sync GEMM (En @ Cn^T·log2e) 128x128 tile, BK=64,
// cp.async double buffer (proven 49.2us config). Epilogue: bare ex2.approx +
// quad-reduce + atomicAdd rowsum, then acq_rel counter; last col-tile CTA
// per row-tile computes the 128-row loss partial (L2-direct __ldcg reads).
// ---------------------------------------------------------------------------
#define GEMM_SMEM 65536

__global__ __launch_bounds__(256, 2)
void gemm_bf16_kernel(float* __restrict__ out) {
    extern __shared__ char smem[];
    const uint32_t sb = smem_to_u32(smem);
    const int tid  = threadIdx.x;
    const int lane = tid & 31;
    const int wid  = tid >> 5;
    const int rowTile = blockIdx.x * 128;
    const int colTile = blockIdx.y * 128;
    const int rowBase = (wid >> 2) * 64;   // warp row  (0 or 64)
    const int colBase = (wid & 3) * 32;    // warp col  (0,32,64,96)

    const int lrow = tid >> 3;   // 0..31 ; rows lrow + 32*j
    const int lseg = tid & 7;    // 16B segment within 128B row

    float acc[4][4][4];
    #pragma unroll
    for (int mi = 0; mi < 4; mi++)
        #pragma unroll
        for (int ni = 0; ni < 4; ni++)
            #pragma unroll
            for (int q = 0; q < 4; q++) acc[mi][ni][q] = 0.0f;

    auto load_chunk = [&](int c, int buf) {
        #pragma unroll
        for (int j = 0; j < 4; j++) {
            int row = lrow + 32 * j;
            uint32_t dst = sb + buf * 32768 + row * 128
                         + ((lseg * 16) ^ ((row & 7) << 4));
            cp16(dst,
                 g_Enh + (size_t)(rowTile + row) * D_DIM + c * 64 + lseg * 8);
            cp16(dst + 16384,
                 g_Cnh + (size_t)(colTile + row) * D_DIM + c * 64 + lseg * 8);
        }
        asm volatile("cp.async.commit_group;" ::: "memory");
    };

    load_chunk(0, 0);
    load_chunk(1, 1);

    #pragma unroll
    for (int c = 0; c < 4; c++) {
        const int buf = c & 1;
        if (c < 3) asm volatile("cp.async.wait_group 1;" ::: "memory");
        else       asm volatile("cp.async.wait_group 0;" ::: "memory");
        __syncthreads();

        const uint32_t aB = sb + buf * 32768;
        const uint32_t bB = aB + 16384;

        #pragma unroll
        for (int ks = 0; ks < 4; ks++) {
            uint32_t a[4][4];
            uint32_t b[4][2];
            #pragma unroll
            for (int mi = 0; mi < 4; mi++) {
                int r = rowBase + mi * 16 + (lane & 15);
                uint32_t addr = aB + r * 128
                    + ((ks * 32 + (lane >> 4) * 16) ^ ((r & 7) << 4));
                asm volatile(
                    "ldmatrix.sync.aligned.m8n8.x4.shared.b16 {%0,%1,%2,%3}, [%4];"
                    : "=r"(a[mi][0]), "=r"(a[mi][1]), "=r"(a[mi][2]), "=r"(a[mi][3])
                    : "r"(addr));
            }
            #pragma unroll
            for (int nn = 0; nn < 2; nn++) {
                int g = lane >> 3;                 // matrix index 0..3
                int r = colBase + (nn * 2 + (g >> 1)) * 8 + (lane & 7);
                uint32_t addr = bB + r * 128
                    + ((ks * 32 + (g & 1) * 16) ^ ((r & 7) << 4));
                asm volatile(
                    "ldmatrix.sync.aligned.m8n8.x4.shared.b16 {%0,%1,%2,%3}, [%4];"
                    : "=r"(b[nn*2][0]), "=r"(b[nn*2][1]),
                      "=r"(b[nn*2+1][0]), "=r"(b[nn*2+1][1])
                    : "r"(addr));
            }
            #pragma unroll
            for (int mi = 0; mi < 4; mi++)
                #pragma unroll
                for (int ni = 0; ni < 4; ni++) {
                    asm volatile(
                        "mma.sync.aligned.m16n8k16.row.col.f32.bf16.bf16.f32 "
                        "{%0,%1,%2,%3}, {%4,%5,%6,%7}, {%8,%9}, {%0,%1,%2,%3};"
                        : "+f"(acc[mi][ni][0]), "+f"(acc[mi][ni][1]),
                          "+f"(acc[mi][ni][2]), "+f"(acc[mi][ni][3])
                        : "r"(a[mi][0]), "r"(a[mi][1]), "r"(a[mi][2]), "r"(a[mi][3]),
                          "r"(b[ni][0]), "r"(b[ni][1]));
                }
        }
        __syncthreads();
        if (c + 2 < 4) load_chunk(c + 2, buf);
    }

    // epilogue: acc holds sim*log2e -> bare ex2 + quad-reduce + atomicAdd
    const int g  = lane >> 2;
    const int tg = lane & 3;
    #pragma unroll
    for (int mi = 0; mi < 4; mi++) {
        float s0 = 0.0f, s1 = 0.0f;
        #pragma unroll
        for (int ni = 0; ni < 4; ni++) {
            s0 += ex2f(acc[mi][ni][0]) + ex2f(acc[mi][ni][1]);
            s1 += ex2f(acc[mi][ni][2]) + ex2f(acc[mi][ni][3]);
        }
        s0 += __shfl_xor_sync(0xffffffffu, s0, 1);
        s0 += __shfl_xor_sync(0xffffffffu, s0, 2);
        s1 += __shfl_xor_sync(0xffffffffu, s1, 1);
        s1 += __shfl_xor_sync(0xffffffffu, s1, 2);
        if (tg == 0) {
            int r = rowTile + rowBase + mi * 16 + g;
            atomicAdd(&g_rowsum[r],     s0);
            atomicAdd(&g_rowsum[r + 8], s1);
        }
    }

    // ---- last-CTA loss fusion via acq_rel flag (no membar, no L1 flush) ----
    __shared__ unsigned doneS;
    __syncthreads();                 // all warps' rowsum atomics before flag
    if (tid == 0) doneS = atom_add_acq_rel(&g_cnt[blockIdx.x], 1u);
    __syncthreads();
    if (doneS == N_COLTILES - 1) {
        if (tid < 128) {
            int r = rowTile + tid;
            float p = g_pos[r];
            float rs = __ldcg(&g_rowsum[r]);     // L2-direct
            float v = __logf(rs - __expf(p)) - p;
            v = warpSum(v);
            if ((tid & 31) == 0) atomicAdd(out, v * (1.0f / B_TOT));
        }
    }
}

// ---------------------------------------------------------------------------
extern "C" void kernel_launch(void* const* d_in, const int* in_sizes, int n_in,
                              void* d_out, int out_size) {
    const float* emb = (const float*)d_in[0];
    float* out = (float*)d_out;

    cudaFuncSetAttribute(gemm_bf16_kernel,
                         cudaFuncAttributeMaxDynamicSharedMemorySize,
                         GEMM_SMEM);

    pre_kernel<<<S_CLS, 320>>>(emb, out);
    dim3 grid(N_ROWTILES, N_COLTILES);
    gemm_bf16_kernel<<<grid, 256, GEMM_SMEM>>>(out);
}

// round 14
// speedup vs baseline: 1.2876x; 1.2876x over previous
#include <cuda_runtime.h>
#include <cuda_bf16.h>
#include <cstdint>
#include <math.h>

// Problem constants (fixed by setup_inputs: S=2048, U=10, D=256)
#define B_TOT 20480
#define D_DIM 256
#define S_CLS 2048
#define U_UTT 10
#define EPSF  1e-8f
#define LOG2E 1.4426950408889634f

// Scratch (static __device__ arrays: allocation-free per harness rules)
__device__ __nv_bfloat16 g_Enh[(size_t)B_TOT * D_DIM];  // normalized embeddings bf16
__device__ __nv_bfloat16 g_Cnh[(size_t)S_CLS * D_DIM];  // normalized centroids bf16 (x log2e)
__device__ float g_rowsum[B_TOT];                       // sum_k exp(sim[row,k])
__device__ float g_pos[B_TOT];                          // sim[row, label(row)]

// ===========================================================================
// helpers
// ===========================================================================
__device__ __forceinline__ uint32_t smem_to_u32(const void* p) {
    uint32_t a;
    asm("{ .reg .u64 t; cvta.to.shared.u64 t, %1; cvt.u32.u64 %0, t; }"
        : "=r"(a) : "l"(p));
    return a;
}
__device__ __forceinline__ void cp16(uint32_t dst, const void* src) {
    asm volatile("cp.async.cg.shared.global [%0], [%1], 16;"
                 :: "r"(dst), "l"(src) : "memory");
}
__device__ __forceinline__ float warpSum(float v) {
    #pragma unroll
    for (int o = 16; o; o >>= 1) v += __shfl_xor_sync(0xffffffffu, v, o);
    return v;
}
__device__ __forceinline__ float dot4(float4 a, float4 b) {
    return a.x*b.x + a.y*b.y + a.z*b.z + a.w*b.w;
}
__device__ __forceinline__ uint32_t pack_bf16x2(float lo, float hi) {
    __nv_bfloat162 p = __float22bfloat162_rn(make_float2(lo, hi));
    return *reinterpret_cast<uint32_t*>(&p);
}
__device__ __forceinline__ float ex2f(float x) {
    float r;
    asm("ex2.approx.ftz.f32 %0, %1;" : "=f"(r) : "f"(x));
    return r;
}

// ---------------------------------------------------------------------------
// Kernel 1 (fused pre-pass): block per speaker, 320 threads = 10 warps.
// Centroid (cross-warp smem sum) -> L2 norm -> g_Cnh scaled by log2e.
// Rows L2-normalized -> g_Enh. pos[row] fp32 vs unscaled smem centroid.
// Zeroes this speaker's 10 rowsum slots and (block 0) out[0].
// ---------------------------------------------------------------------------
__global__ __launch_bounds__(320)
void pre_kernel(const float* __restrict__ emb, float* __restrict__ out) {
    __shared__ __align__(16) float rowS[U_UTT][D_DIM];
    __shared__ __align__(16) float cnS[D_DIM];
    __shared__ float red[16];
    const int s    = blockIdx.x;
    const int u    = threadIdx.x >> 5;
    const int lane = threadIdx.x & 31;
    const int t    = threadIdx.x;
    if (s == 0 && t == 0) out[0] = 0.0f;
    if (t < U_UTT) g_rowsum[s * U_UTT + t] = 0.0f;

    const float4* pr = (const float4*)(emb + ((size_t)s * U_UTT + u) * D_DIM);
    float4 a = pr[lane], b = pr[lane + 32];
    ((float4*)rowS[u])[lane]      = a;
    ((float4*)rowS[u])[lane + 32] = b;
    __syncthreads();

    float c = 0.0f;
    if (t < D_DIM) {
        #pragma unroll
        for (int uu = 0; uu < U_UTT; uu++) c += rowS[uu][t];
        c *= (1.0f / U_UTT);
    }
    float sq = warpSum(c * c);
    if (lane == 0) red[u] = sq;
    __syncthreads();
    if (t < 32) {
        float v = (lane < U_UTT) ? red[lane] : 0.0f;
        v = warpSum(v);
        if (lane == 0) red[0] = v;
    }
    __syncthreads();
    const float cnorm = fmaxf(sqrtf(red[0]), EPSF);
    if (t < D_DIM) {
        float cn = c / cnorm;
        cnS[t] = cn;
        g_Cnh[(size_t)s * D_DIM + t] = __float2bfloat16(cn * LOG2E);
    }
    __syncthreads();

    float sqr = warpSum(dot4(a, a) + dot4(b, b));
    float sc = 1.0f / fmaxf(sqrtf(sqr), EPSF);
    a.x *= sc; a.y *= sc; a.z *= sc; a.w *= sc;
    b.x *= sc; b.y *= sc; b.z *= sc; b.w *= sc;
    const size_t row = (size_t)s * U_UTT + u;
    uint2* outh = (uint2*)(g_Enh + row * D_DIM);
    outh[lane]      = make_uint2(pack_bf16x2(a.x, a.y), pack_bf16x2(a.z, a.w));
    outh[lane + 32] = make_uint2(pack_bf16x2(b.x, b.y), pack_bf16x2(b.z, b.w));
    const float4* pc = (const float4*)cnS;
    float v = dot4(a, pc[lane]) + dot4(b, pc[lane + 32]);
    v = warpSum(v);
    if (lane == 0) g_pos[row] = v;
}

// ---------------------------------------------------------------------------
// Kernel 2: bf16 mma.sync GEMM (En @ Cn^T·log2e) 128x128 tile, BK=64,
// RING-3 cp.async pipeline (one __syncthreads per stage; stages 0-2
// pre-issued, stage 3 issued after the c==1 barrier frees buf0).
// Epilogue: bare ex2.approx + quad-reduce + atomicAdd rowsum.
// smem: 3 buffers x 32KB = 96KB; occ 2.
// ---------------------------------------------------------------------------
#define GEMM_SMEM 98304

__global__ __launch_bounds__(256, 2)
void gemm_bf16_kernel() {
    extern __shared__ char smem[];
    const uint32_t sb = smem_to_u32(smem);
    const int tid  = threadIdx.x;
    const int lane = tid & 31;
    const int wid  = tid >> 5;
    const int rowTile = blockIdx.x * 128;
    const int colTile = blockIdx.y * 128;
    const int rowBase = (wid >> 2) * 64;   // warp row  (0 or 64)
    const int colBase = (wid & 3) * 32;    // warp col  (0,32,64,96)

    const int lrow = tid >> 3;   // 0..31 ; rows lrow + 32*j
    const int lseg = tid & 7;    // 16B segment within 128B row

    float acc[4][4][4];
    #pragma unroll
    for (int mi = 0; mi < 4; mi++)
        #pragma unroll
        for (int ni = 0; ni < 4; ni++)
            #pragma unroll
            for (int q = 0; q < 4; q++) acc[mi][ni][q] = 0.0f;

    auto load_chunk = [&](int c, int buf) {
        #pragma unroll
        for (int j = 0; j < 4; j++) {
            int row = lrow + 32 * j;
            uint32_t dst = sb + buf * 32768 + row * 128
                         + ((lseg * 16) ^ ((row & 7) << 4));
            cp16(dst,
                 g_Enh + (size_t)(rowTile + row) * D_DIM + c * 64 + lseg * 8);
            cp16(dst + 16384,
                 g_Cnh + (size_t)(colTile + row) * D_DIM + c * 64 + lseg * 8);
        }
        asm volatile("cp.async.commit_group;" ::: "memory");
    };

    // pre-issue stages 0,1,2 into ring slots 0,1,2
    load_chunk(0, 0);
    load_chunk(1, 1);
    load_chunk(2, 2);

    #pragma unroll
    for (int c = 0; c < 4; c++) {
        if (c == 0)      asm volatile("cp.async.wait_group 2;" ::: "memory");
        else if (c == 3) asm volatile("cp.async.wait_group 0;" ::: "memory");
        else             asm volatile("cp.async.wait_group 1;" ::: "memory");
        __syncthreads();   // stage c visible everywhere; compute(c-1) done

        if (c == 1) load_chunk(3, 0);   // buf0 free after c==1 barrier

        const int buf = (c == 3) ? 0 : c;
        const uint32_t aB = sb + buf * 32768;
        const uint32_t bB = aB + 16384;

        #pragma unroll
        for (int ks = 0; ks < 4; ks++) {
            uint32_t a[4][4];
            uint32_t b[4][2];
            #pragma unroll
            for (int mi = 0; mi < 4; mi++) {
                int r = rowBase + mi * 16 + (lane & 15);
                uint32_t addr = aB + r * 128
                    + ((ks * 32 + (lane >> 4) * 16) ^ ((r & 7) << 4));
                asm volatile(
                    "ldmatrix.sync.aligned.m8n8.x4.shared.b16 {%0,%1,%2,%3}, [%4];"
                    : "=r"(a[mi][0]), "=r"(a[mi][1]), "=r"(a[mi][2]), "=r"(a[mi][3])
                    : "r"(addr));
            }
            #pragma unroll
            for (int nn = 0; nn < 2; nn++) {
                int g = lane >> 3;                 // matrix index 0..3
                int r = colBase + (nn * 2 + (g >> 1)) * 8 + (lane & 7);
                uint32_t addr = bB + r * 128
                    + ((ks * 32 + (g & 1) * 16) ^ ((r & 7) << 4));
                asm volatile(
                    "ldmatrix.sync.aligned.m8n8.x4.shared.b16 {%0,%1,%2,%3}, [%4];"
                    : "=r"(b[nn*2][0]), "=r"(b[nn*2][1]),
                      "=r"(b[nn*2+1][0]), "=r"(b[nn*2+1][1])
                    : "r"(addr));
            }
            #pragma unroll
            for (int mi = 0; mi < 4; mi++)
                #pragma unroll
                for (int ni = 0; ni < 4; ni++) {
                    asm volatile(
                        "mma.sync.aligned.m16n8k16.row.col.f32.bf16.bf16.f32 "
                        "{%0,%1,%2,%3}, {%4,%5,%6,%7}, {%8,%9}, {%0,%1,%2,%3};"
                        : "+f"(acc[mi][ni][0]), "+f"(acc[mi][ni][1]),
                          "+f"(acc[mi][ni][2]), "+f"(acc[mi][ni][3])
                        : "r"(a[mi][0]), "r"(a[mi][1]), "r"(a[mi][2]), "r"(a[mi][3]),
                          "r"(b[ni][0]), "r"(b[ni][1]));
                }
        }
    }

    // epilogue: acc holds sim*log2e -> bare ex2 + quad-reduce + atomicAdd
    const int g  = lane >> 2;
    const int tg = lane & 3;
    #pragma unroll
    for (int mi = 0; mi < 4; mi++) {
        float s0 = 0.0f, s1 = 0.0f;
        #pragma unroll
        for (int ni = 0; ni < 4; ni++) {
            s0 += ex2f(acc[mi][ni][0]) + ex2f(acc[mi][ni][1]);
            s1 += ex2f(acc[mi][ni][2]) + ex2f(acc[mi][ni][3]);
        }
        s0 += __shfl_xor_sync(0xffffffffu, s0, 1);
        s0 += __shfl_xor_sync(0xffffffffu, s0, 2);
        s1 += __shfl_xor_sync(0xffffffffu, s1, 1);
        s1 += __shfl_xor_sync(0xffffffffu, s1, 2);
        if (tg == 0) {
            int r = rowTile + rowBase + mi * 16 + g;
            atomicAdd(&g_rowsum[r],     s0);
            atomicAdd(&g_rowsum[r + 8], s1);
        }
    }
}

// ---------------------------------------------------------------------------
// Kernel 3: loss partials -> atomicAdd into out[0] (zeroed by pre_kernel).
// ---------------------------------------------------------------------------
__global__ void loss_kernel(float* __restrict__ out) {
    int i = blockIdx.x * 256 + threadIdx.x;
    float p = g_pos[i];
    float acc = __logf(g_rowsum[i] - __expf(p)) - p;
    __shared__ float sh[8];
    int lane = threadIdx.x & 31, w = threadIdx.x >> 5;
    acc = warpSum(acc);
    if (lane == 0) sh[w] = acc;
    __syncthreads();
    if (w == 0) {
        acc = (lane < 8) ? sh[lane] : 0.0f;
        #pragma unroll
        for (int o = 4; o; o >>= 1) acc += __shfl_xor_sync(0xffffffffu, acc, o);
        if (lane == 0) atomicAdd(out, acc * (1.0f / B_TOT));
    }
}

// ---------------------------------------------------------------------------
extern "C" void kernel_launch(void* const* d_in, const int* in_sizes, int n_in,
                              void* d_out, int out_size) {
    const float* emb = (const float*)d_in[0];
    float* out = (float*)d_out;

    // Pin one carveout config for ALL kernels (avoid per-node carveout switches)
    cudaFuncSetAttribute(gemm_bf16_kernel,
                         cudaFuncAttributeMaxDynamicSharedMemorySize,
                         GEMM_SMEM);
    cudaFuncSetAttribute(gemm_bf16_kernel,
                         cudaFuncAttributePreferredSharedMemoryCarveout, 100);
    cudaFuncSetAttribute(pre_kernel,
                         cudaFuncAttributePreferredSharedMemoryCarveout, 100);
    cudaFuncSetAttribute(loss_kernel,
                         cudaFuncAttributePreferredSharedMemoryCarveout, 100);

    pre_kernel<<<S_CLS, 320>>>(emb, out);
    dim3 grid(B_TOT / 128, S_CLS / 128);
    gemm_bf16_kernel<<<grid, 256, GEMM_SMEM>>>();
    loss_kernel<<<B_TOT / 256, 256>>>(out);
}

// round 15
// speedup vs baseline: 1.2883x; 1.0006x over previous
#include <cuda_runtime.h>
#include <cuda_bf16.h>
#include <cstdint>
#include <math.h>

// Problem constants (fixed by setup_inputs: S=2048, U=10, D=256)
#define B_TOT 20480
#define D_DIM 256
#define S_CLS 2048
#define U_UTT 10
#define EPSF  1e-8f
#define LOG2E 1.4426950408889634f

// Scratch (static __device__ arrays: allocation-free per harness rules)
__device__ __nv_bfloat16 g_Enh[(size_t)B_TOT * D_DIM];  // normalized embeddings bf16
__device__ __nv_bfloat16 g_Cnh[(size_t)S_CLS * D_DIM];  // normalized centroids bf16 (x log2e)
__device__ float g_rowsum[B_TOT];                       // sum_k exp(sim[row,k])
__device__ float g_pos[B_TOT];                          // sim[row, label(row)]

// ===========================================================================
// helpers
// ===========================================================================
__device__ __forceinline__ uint32_t smem_to_u32(const void* p) {
    uint32_t a;
    asm("{ .reg .u64 t; cvta.to.shared.u64 t, %1; cvt.u32.u64 %0, t; }"
        : "=r"(a) : "l"(p));
    return a;
}
__device__ __forceinline__ void cp16(uint32_t dst, const void* src) {
    asm volatile("cp.async.cg.shared.global [%0], [%1], 16;"
                 :: "r"(dst), "l"(src) : "memory");
}
__device__ __forceinline__ float warpSum(float v) {
    #pragma unroll
    for (int o = 16; o; o >>= 1) v += __shfl_xor_sync(0xffffffffu, v, o);
    return v;
}
__device__ __forceinline__ float dot4(float4 a, float4 b) {
    return a.x*b.x + a.y*b.y + a.z*b.z + a.w*b.w;
}
__device__ __forceinline__ uint32_t pack_bf16x2(float lo, float hi) {
    __nv_bfloat162 p = __float22bfloat162_rn(make_float2(lo, hi));
    return *reinterpret_cast<uint32_t*>(&p);
}
__device__ __forceinline__ float ex2f(float x) {
    float r;
    asm("ex2.approx.ftz.f32 %0, %1;" : "=f"(r) : "f"(x));
    return r;
}

// ---------------------------------------------------------------------------
// Kernel 1 (fused pre-pass): block per speaker, 320 threads = 10 warps.
// Critical-path-trimmed: row normalize + g_Enh store hoisted before the
// centroid phase; cross-warp reduce done redundantly per-thread from smem
// (no warp-0 serial stage); 3 __syncthreads total.
// Zeroes this speaker's 10 rowsum slots and (block 0) out[0].
// ---------------------------------------------------------------------------
__global__ __launch_bounds__(320)
void pre_kernel(const float* __restrict__ emb, float* __restrict__ out) {
    __shared__ __align__(16) float rowS[U_UTT][D_DIM];
    __shared__ __align__(16) float cnS[D_DIM];
    __shared__ float red[U_UTT];
    const int s    = blockIdx.x;
    const int u    = threadIdx.x >> 5;
    const int lane = threadIdx.x & 31;
    const int t    = threadIdx.x;
    if (s == 0 && t == 0) out[0] = 0.0f;
    if (t < U_UTT) g_rowsum[s * U_UTT + t] = 0.0f;

    // load row u, mirror raw values to smem (centroid needs raw data)
    const float4* pr = (const float4*)(emb + ((size_t)s * U_UTT + u) * D_DIM);
    float4 a = pr[lane], b = pr[lane + 32];
    ((float4*)rowS[u])[lane]      = a;
    ((float4*)rowS[u])[lane + 32] = b;

    // row normalize + g_Enh store: warp-local, independent of other warps —
    // overlaps the mirror-store latency of the rest of the block
    float sqr = warpSum(dot4(a, a) + dot4(b, b));
    float sc = 1.0f / fmaxf(sqrtf(sqr), EPSF);
    a.x *= sc; a.y *= sc; a.z *= sc; a.w *= sc;
    b.x *= sc; b.y *= sc; b.z *= sc; b.w *= sc;
    const size_t row = (size_t)s * U_UTT + u;
    uint2* outh = (uint2*)(g_Enh + row * D_DIM);
    outh[lane]      = make_uint2(pack_bf16x2(a.x, a.y), pack_bf16x2(a.z, a.w));
    outh[lane + 32] = make_uint2(pack_bf16x2(b.x, b.y), pack_bf16x2(b.z, b.w));
    __syncthreads();                       // (1) rowS complete

    // centroid: threads 0..255 own dim t; warps 8,9 contribute zero partials
    float c = 0.0f;
    if (t < D_DIM) {
        #pragma unroll
        for (int uu = 0; uu < U_UTT; uu++) c += rowS[uu][t];
        c *= (1.0f / U_UTT);
    }
    float sq = warpSum(c * c);
    if (lane == 0) red[u] = sq;
    __syncthreads();                       // (2) red complete

    // every thread sums the 10 warp partials (off the serial path)
    float tot = 0.0f;
    #pragma unroll
    for (int i = 0; i < U_UTT; i++) tot += red[i];
    const float cnorm = fmaxf(sqrtf(tot), EPSF);
    if (t < D_DIM) {
        float cn = c / cnorm;
        cnS[t] = cn;
        g_Cnh[(size_t)s * D_DIM + t] = __float2bfloat16(cn * LOG2E);
    }
    __syncthreads();                       // (3) cnS complete

    // pos = dot(normalized row, centroid)
    const float4* pc = (const float4*)cnS;
    float v = dot4(a, pc[lane]) + dot4(b, pc[lane + 32]);
    v = warpSum(v);
    if (lane == 0) g_pos[row] = v;
}

// ---------------------------------------------------------------------------
// Kernel 2: bf16 mma.sync GEMM (En @ Cn^T·log2e) 128x128 tile, BK=64,
// cp.async double buffer (proven R12 config, byte-identical). Accumulator
// holds sim*log2e; epilogue is bare ex2.approx + quad-reduce + atomicAdd.
// ---------------------------------------------------------------------------
#define GEMM_SMEM 65536

__global__ __launch_bounds__(256, 2)
void gemm_bf16_kernel() {
    extern __shared__ char smem[];
    const uint32_t sb = smem_to_u32(smem);
    const int tid  = threadIdx.x;
    const int lane = tid & 31;
    const int wid  = tid >> 5;
    const int rowTile = blockIdx.x * 128;
    const int colTile = blockIdx.y * 128;
    const int rowBase = (wid >> 2) * 64;   // warp row  (0 or 64)
    const int colBase = (wid & 3) * 32;    // warp col  (0,32,64,96)

    const int lrow = tid >> 3;   // 0..31 ; rows lrow + 32*j
    const int lseg = tid & 7;    // 16B segment within 128B row

    float acc[4][4][4];
    #pragma unroll
    for (int mi = 0; mi < 4; mi++)
        #pragma unroll
        for (int ni = 0; ni < 4; ni++)
            #pragma unroll
            for (int q = 0; q < 4; q++) acc[mi][ni][q] = 0.0f;

    auto load_chunk = [&](int c, int buf) {
        #pragma unroll
        for (int j = 0; j < 4; j++) {
            int row = lrow + 32 * j;
            uint32_t dst = sb + buf * 32768 + row * 128
                         + ((lseg * 16) ^ ((row & 7) << 4));
            cp16(dst,
                 g_Enh + (size_t)(rowTile + row) * D_DIM + c * 64 + lseg * 8);
            cp16(dst + 16384,
                 g_Cnh + (size_t)(colTile + row) * D_DIM + c * 64 + lseg * 8);
        }
        asm volatile("cp.async.commit_group;" ::: "memory");
    };

    load_chunk(0, 0);
    load_chunk(1, 1);

    #pragma unroll
    for (int c = 0; c < 4; c++) {
        const int buf = c & 1;
        if (c < 3) asm volatile("cp.async.wait_group 1;" ::: "memory");
        else       asm volatile("cp.async.wait_group 0;" ::: "memory");
        __syncthreads();

        const uint32_t aB = sb + buf * 32768;
        const uint32_t bB = aB + 16384;

        #pragma unroll
        for (int ks = 0; ks < 4; ks++) {
            uint32_t a[4][4];
            uint32_t b[4][2];
            #pragma unroll
            for (int mi = 0; mi < 4; mi++) {
                int r = rowBase + mi * 16 + (lane & 15);
                uint32_t addr = aB + r * 128
                    + ((ks * 32 + (lane >> 4) * 16) ^ ((r & 7) << 4));
                asm volatile(
                    "ldmatrix.sync.aligned.m8n8.x4.shared.b16 {%0,%1,%2,%3}, [%4];"
                    : "=r"(a[mi][0]), "=r"(a[mi][1]), "=r"(a[mi][2]), "=r"(a[mi][3])
                    : "r"(addr));
            }
            #pragma unroll
            for (int nn = 0; nn < 2; nn++) {
                int g = lane >> 3;                 // matrix index 0..3
                int r = colBase + (nn * 2 + (g >> 1)) * 8 + (lane & 7);
                uint32_t addr = bB + r * 128
                    + ((ks * 32 + (g & 1) * 16) ^ ((r & 7) << 4));
                asm volatile(
                    "ldmatrix.sync.aligned.m8n8.x4.shared.b16 {%0,%1,%2,%3}, [%4];"
                    : "=r"(b[nn*2][0]), "=r"(b[nn*2][1]),
                      "=r"(b[nn*2+1][0]), "=r"(b[nn*2+1][1])
                    : "r"(addr));
            }
            #pragma unroll
            for (int mi = 0; mi < 4; mi++)
                #pragma unroll
                for (int ni = 0; ni < 4; ni++) {
                    asm volatile(
                        "mma.sync.aligned.m16n8k16.row.col.f32.bf16.bf16.f32 "
                        "{%0,%1,%2,%3}, {%4,%5,%6,%7}, {%8,%9}, {%0,%1,%2,%3};"
                        : "+f"(acc[mi][ni][0]), "+f"(acc[mi][ni][1]),
                          "+f"(acc[mi][ni][2]), "+f"(acc[mi][ni][3])
                        : "r"(a[mi][0]), "r"(a[mi][1]), "r"(a[mi][2]), "r"(a[mi][3]),
                          "r"(b[ni][0]), "r"(b[ni][1]));
                }
        }
        __syncthreads();
        if (c + 2 < 4) load_chunk(c + 2, buf);
    }

    // epilogue: acc holds sim*log2e -> bare ex2 + quad-reduce + atomicAdd
    const int g  = lane >> 2;
    const int tg = lane & 3;
    #pragma unroll
    for (int mi = 0; mi < 4; mi++) {
        float s0 = 0.0f, s1 = 0.0f;
        #pragma unroll
        for (int ni = 0; ni < 4; ni++) {
            s0 += ex2f(acc[mi][ni][0]) + ex2f(acc[mi][ni][1]);
            s1 += ex2f(acc[mi][ni][2]) + ex2f(acc[mi][ni][3]);
        }
        s0 += __shfl_xor_sync(0xffffffffu, s0, 1);
        s0 += __shfl_xor_sync(0xffffffffu, s0, 2);
        s1 += __shfl_xor_sync(0xffffffffu, s1, 1);
        s1 += __shfl_xor_sync(0xffffffffu, s1, 2);
        if (tg == 0) {
            int r = rowTile + rowBase + mi * 16 + g;
            atomicAdd(&g_rowsum[r],     s0);
            atomicAdd(&g_rowsum[r + 8], s1);
        }
    }
}

// ---------------------------------------------------------------------------
// Kernel 3: loss partials -> atomicAdd into out[0] (zeroed by pre_kernel).
// ---------------------------------------------------------------------------
__global__ void loss_kernel(float* __restrict__ out) {
    int i = blockIdx.x * 256 + threadIdx.x;
    float p = g_pos[i];
    float acc = __logf(g_rowsum[i] - __expf(p)) - p;
    __shared__ float sh[8];
    int lane = threadIdx.x & 31, w = threadIdx.x >> 5;
    acc = warpSum(acc);
    if (lane == 0) sh[w] = acc;
    __syncthreads();
    if (w == 0) {
        acc = (lane < 8) ? sh[lane] : 0.0f;
        #pragma unroll
        for (int o = 4; o; o >>= 1) acc += __shfl_xor_sync(0xffffffffu, acc, o);
        if (lane == 0) atomicAdd(out, acc * (1.0f / B_TOT));
    }
}

// ---------------------------------------------------------------------------
extern "C" void kernel_launch(void* const* d_in, const int* in_sizes, int n_in,
                              void* d_out, int out_size) {
    const float* emb = (const float*)d_in[0];
    float* out = (float*)d_out;

    cudaFuncSetAttribute(gemm_bf16_kernel,
                         cudaFuncAttributeMaxDynamicSharedMemorySize,
                         GEMM_SMEM);

    pre_kernel<<<S_CLS, 320>>>(emb, out);
    dim3 grid(B_TOT / 128, S_CLS / 128);
    gemm_bf16_kernel<<<grid, 256, GEMM_SMEM>>>();
    loss_kernel<<<B_TOT / 256, 256>>>(out);
}